// round 8
// baseline (speedup 1.0000x reference)
#include <cuda_runtime.h>
#include <math_constants.h>

// VQ-VAE vector quantizer. Bitwise-emulates the reference fp32 pipeline:
//   d_k = fl32( fl32(A - 2*M_k) + B_k )
//   A   = sum(x^2)  (float2 leaves + binary tree)   [frozen order]
//   M_k = x . e_k   (sequential ascending-d fp32 FMA chain from 0) [frozen]
//   B_k = sum(e^2)  (sequential ascending chain)    [frozen]
//   argmin, tie -> lowest index.
//
// R8: K-split x4 (grid 2048, 2 chunks/block) -> 6.92->7 waves (98.9% packing
// vs 86.5%). Partial argmins combined via u64 atomicMin with order-isomorphic
// key (d_bits<<32 | idx; d>0 always). Last sibling block per tile runs the
// epilogue from its own smem X tile. Inner loop identical to R7.

#define K_CODES   1024
#define D_DIM     64
#define TP        128     // positions per tile
#define TK        128     // codes per chunk
#define NCHUNK    2       // chunks per block (256 codes)
#define NSPLIT    4       // blocks per tile
#define NTILES    512
#define EROW      132     // E row stride in floats (16B-aligned)
#define EBUF      (64 * EROW)
#define ENC_OFF   4194304
#define LOSS_OFF  4259840
#define NLL_OFF   4259841
#define TOTAL_OUT 4259842

typedef unsigned long long ull;

__device__ double g_loss_acc;
__device__ int    g_fin;
__device__ int    g_tcnt[NTILES];
__device__ float  g_eB[K_CODES];     // fp32 ||e_k||^2, sequential chain
__device__ ull    g_best[65536];     // packed (d_bits<<32 | idx) per position

// ---- packed f32x2 helpers (sm_100+); each lane rounds like scalar op ----
__device__ __forceinline__ ull pk2(float a, float b) {
    ull r; asm("mov.b64 %0, {%1, %2};" : "=l"(r) : "f"(a), "f"(b)); return r;
}
__device__ __forceinline__ void upk2(ull v, float& a, float& b) {
    asm("mov.b64 {%0, %1}, %2;" : "=f"(a), "=f"(b) : "l"(v));
}
__device__ __forceinline__ ull ffma2(ull a, ull b, ull c) {
    ull r; asm("fma.rn.f32x2 %0, %1, %2, %3;" : "=l"(r) : "l"(a), "l"(b), "l"(c)); return r;
}
__device__ __forceinline__ ull add2(ull a, ull b) {
    ull r; asm("add.rn.f32x2 %0, %1, %2;" : "=l"(r) : "l"(a), "l"(b)); return r;
}

// Kernel 0: resets + B_k chains.
__global__ void __launch_bounds__(256) vq_prep(const float* __restrict__ emb) {
    int t = blockIdx.x * blockDim.x + threadIdx.x;   // 256*256 = 65536
    g_best[t] = ~0ull;
    if (t < NTILES) g_tcnt[t] = 0;
    if (t == 0) { g_loss_acc = 0.0; g_fin = 0; }
    if (t < K_CODES) {
        const float* row = emb + (size_t)t * D_DIM;
        float b = 0.0f;
        #pragma unroll
        for (int i = 0; i < 16; i++) {
            float4 v = *(const float4*)(row + i * 4);
            b = __fmaf_rn(v.x, v.x, b);
            b = __fmaf_rn(v.y, v.y, b);
            b = __fmaf_rn(v.z, v.z, b);
            b = __fmaf_rn(v.w, v.w, b);
        }
        g_eB[t] = b;
    }
}

// Main kernel: one block = 128 positions x 256 codes (one K-quarter).
__global__ void __launch_bounds__(256, 2) vq_main(const float* __restrict__ x,
                                                  const float* __restrict__ emb,
                                                  float* __restrict__ out,
                                                  int out_size) {
    extern __shared__ char smem_raw[];
    float* Xs   = (float*)smem_raw;                        // [64][128]     32768 B
    float* Es   = (float*)(smem_raw + 32768);              // [2][64][132]  67584 B
    float* Bs   = (float*)(smem_raw + 32768 + 67584);      // [2][128]       1024 B
    float* As   = (float*)(smem_raw + 101376);             // [128]           512 B
    int*   idx_s = (int*)(smem_raw + 101888);              // [128]           512 B
    // reduction overlays Es buffer 0 (only used after both chunks done):
    float* rV = Es;                                        // [8][128]
    int*   rI = (int*)Es + 1024;                           // [8][128]
    __shared__ int s_flag;

    const int tid = threadIdx.x;
    const int tx = tid & 31;            // position group (4 positions)
    const int ty = tid >> 5;            // code group (16 codes) — warp-uniform
    const int tile = blockIdx.x >> 2;
    const int ks   = blockIdx.x & 3;    // K-quarter
    const int b  = tile >> 3;
    const int p0 = (tile & 7) * TP;
    const int gbase = b * 1024 + p0;    // global position base
    const int st_dc = tid & 15;         // staging d-chunk (float4)
    const int st_s  = st_dc >> 1;       // staging swizzle const (= d>>3)
    const int krow  = tid >> 4;

    // ---- load X tile: Xs[d][pp] = x[(b*64+d)*1024 + p0 + pp] ----
    {
        const float* xb = x + (size_t)b * 65536 + p0;
        int chunk = tid & 31;
        int r0    = tid >> 5;
        #pragma unroll
        for (int it = 0; it < 8; it++) {
            int d = r0 + it * 8;
            float4 v = *(const float4*)(xb + d * 1024 + chunk * 4);
            *(float4*)&Xs[d * TP + chunk * 4] = v;
        }
    }
    __syncthreads();

    // ---- A_p = sum(x^2): float2 leaves + binary tree (frozen order) ----
    if (tid < TP) {
        float l[32];
        #pragma unroll
        for (int t = 0; t < 32; t++) {
            float a = Xs[(2 * t) * TP + tid];
            float c = Xs[(2 * t + 1) * TP + tid];
            l[t] = __fmaf_rn(c, c, __fmul_rn(a, a));
        }
        #pragma unroll
        for (int off = 16; off >= 1; off >>= 1)
            #pragma unroll
            for (int t = 0; t < 16; t++)
                if (t < off) l[t] = __fadd_rn(l[t], l[t + off]);
        As[tid] = l[0];
    }
    __syncthreads();

    const ull neg2 = pk2(-2.0f, -2.0f);
    float bv[4];
    int   bi[4];
    #pragma unroll
    for (int i = 0; i < 4; i++) { bv[i] = CUDART_INF_F; bi[i] = 0; }

    // ---- 2 chunks: stage(c) -> sync -> compute(c); double buffer ----
    #pragma unroll 1
    for (int ci = 0; ci < NCHUNK; ci++) {
        const int k0 = (ks * NCHUNK + ci) * TK;
        float* Eb = Es + ci * EBUF;
        float* Bb = Bs + ci * TK;

        // stage E chunk, transposed + granule-XOR swizzle:
        //   element (d, k) -> word d*EROW + (((k>>2) ^ (d>>3)) << 2) + (k&3)
        {
            #pragma unroll
            for (int it = 0; it < 8; it++) {
                int k = krow + it * 16;
                float4 v = *(const float4*)(emb + (size_t)(k0 + k) * 64 + st_dc * 4);
                int swc = ((((k >> 2) ^ st_s) << 2) + (k & 3));
                Eb[(st_dc * 4 + 0) * EROW + swc] = v.x;
                Eb[(st_dc * 4 + 1) * EROW + swc] = v.y;
                Eb[(st_dc * 4 + 2) * EROW + swc] = v.z;
                Eb[(st_dc * 4 + 3) * EROW + swc] = v.w;
            }
            if (tid < TK) Bb[tid] = g_eB[k0 + tid];
        }
        __syncthreads();

        // compute: acc[4 pos][8 pairs] (16 codes), ascending-d chains
        ull acc[4][8];
        #pragma unroll
        for (int p = 0; p < 4; p++)
            #pragma unroll
            for (int kk = 0; kk < 8; kk++) acc[p][kk] = 0ull;

        #pragma unroll
        for (int d8 = 0; d8 < 8; d8++) {
            int goff0 = (((4 * ty + 0) ^ d8) << 2);
            int goff1 = (((4 * ty + 1) ^ d8) << 2);
            int goff2 = (((4 * ty + 2) ^ d8) << 2);
            int goff3 = (((4 * ty + 3) ^ d8) << 2);
            #pragma unroll
            for (int dj = 0; dj < 8; dj++) {
                const int d = d8 * 8 + dj;
                const float* Ed = Eb + d * EROW;
                ulonglong2 e01 = *(const ulonglong2*)(Ed + goff0);
                ulonglong2 e23 = *(const ulonglong2*)(Ed + goff1);
                ulonglong2 e45 = *(const ulonglong2*)(Ed + goff2);
                ulonglong2 e67 = *(const ulonglong2*)(Ed + goff3);
                float4 xv = *(const float4*)&Xs[d * TP + tx * 4];
                ull ep[8] = { e01.x, e01.y, e23.x, e23.y,
                              e45.x, e45.y, e67.x, e67.y };
                float xs4[4] = { xv.x, xv.y, xv.z, xv.w };
                #pragma unroll
                for (int p = 0; p < 4; p++) {
                    ull xp = pk2(xs4[p], xs4[p]);
                    #pragma unroll
                    for (int kk = 0; kk < 8; kk++)
                        acc[p][kk] = ffma2(xp, ep[kk], acc[p][kk]);
                }
            }
        }

        // fold: d = fl(fl(A - 2M) + B); even code first -> lowest idx on tie
        #pragma unroll
        for (int p = 0; p < 4; p++) {
            float Ap = As[tx * 4 + p];
            ull Apk = pk2(Ap, Ap);
            #pragma unroll
            for (int kk = 0; kk < 8; kk++) {
                ull B2 = ((const ull*)Bb)[ty * 8 + kk];
                ull dpk = add2(ffma2(neg2, acc[p][kk], Apk), B2);
                float d0, d1;
                upk2(dpk, d0, d1);
                int ke = k0 + ty * 16 + 2 * kk;
                if (d0 < bv[p]) { bv[p] = d0; bi[p] = ke; }
                if (d1 < bv[p]) { bv[p] = d1; bi[p] = ke + 1; }
            }
        }
        __syncthreads();   // compute done before next stage / overlay
    }

    // ---- cross-ty reduction, then global combine via atomicMin ----
    #pragma unroll
    for (int p = 0; p < 4; p++) {
        rV[ty * TP + tx * 4 + p] = bv[p];
        rI[ty * TP + tx * 4 + p] = bi[p];
    }
    __syncthreads();
    if (tid < TP) {
        float best = rV[tid];
        int besti  = rI[tid];
        #pragma unroll
        for (int t = 1; t < 8; t++) {
            float v = rV[t * TP + tid];
            int iv  = rI[t * TP + tid];
            if (v < best || (v == best && iv < besti)) { best = v; besti = iv; }
        }
        // d > 0 always -> float bits order-isomorphic; tie -> lowest idx
        ull key = ((ull)__float_as_uint(best) << 32) | (unsigned)besti;
        atomicMin(&g_best[gbase + tid], key);
    }

    // ---- last sibling of this tile runs the epilogue ----
    __syncthreads();
    if (tid == 0) {
        __threadfence();
        int old = atomicAdd(&g_tcnt[tile], 1);
        s_flag = (old == NSPLIT - 1);
    }
    __syncthreads();
    if (!s_flag) return;

    // read final winners (atomicMin with MAX = coherent atomic read)
    if (tid < TP) {
        ull key = atomicMin(&g_best[gbase + tid], ~0ull);
        int idx = (int)(unsigned)key;
        idx_s[tid] = idx;
        if (out_size >= TOTAL_OUT)
            out[ENC_OFF + gbase + tid] = (float)idx;
    }
    __syncthreads();

    // output (straight-through: x + fl(q - x)) + loss partial
    float lsum = 0.0f;
    #pragma unroll
    for (int j = 0; j < 32; j++) {
        int i  = tid + j * 256;
        int pp = i & 127;
        int d  = i >> 7;
        float q2 = emb[(size_t)idx_s[pp] * 64 + d];
        float xv = Xs[d * TP + pp];
        float df = __fadd_rn(q2, -xv);
        lsum += df * df;
        out[((size_t)b * 64 + d) * 1024 + p0 + pp] = __fadd_rn(xv, df);
    }
    #pragma unroll
    for (int off = 16; off > 0; off >>= 1)
        lsum += __shfl_down_sync(0xffffffffu, lsum, off);
    __shared__ float wsum[8];
    if ((tid & 31) == 0) wsum[tid >> 5] = lsum;
    __syncthreads();
    if (tid == 0) {
        float t = 0.0f;
        #pragma unroll
        for (int w = 0; w < 8; w++) t += wsum[w];
        atomicAdd(&g_loss_acc, (double)t);
        __threadfence();
        int old = atomicAdd(&g_fin, 1);
        if (old == NTILES - 1) {               // final tile writes loss + nll
            if (out_size >= TOTAL_OUT) {
                float m = (float)(g_loss_acc * (1.0 / 4194304.0));
                out[LOSS_OFF] = __fadd_rn(m, __fmul_rn(0.25f, m));
                out[NLL_OFF]  = 1.0f;
            }
        }
    }
}

extern "C" void kernel_launch(void* const* d_in, const int* in_sizes, int n_in,
                              void* d_out, int out_size) {
    const float* x   = (const float*)d_in[0];
    const float* emb = (const float*)d_in[1];
    if (n_in >= 2 && in_sizes[0] == K_CODES * D_DIM) {
        const float* t = x; x = emb; emb = t;
    }
    float* out = (float*)d_out;

    const int smem_bytes = 32768 + 67584 + 1024 + 512 + 512;   // 102400
    cudaFuncSetAttribute(vq_main, cudaFuncAttributeMaxDynamicSharedMemorySize,
                         smem_bytes);

    vq_prep<<<256, 256>>>(emb);
    vq_main<<<2048, 256, smem_bytes>>>(x, emb, out, out_size);
}

// round 9
// speedup vs baseline: 1.0383x; 1.0383x over previous
#include <cuda_runtime.h>
#include <math_constants.h>

// VQ-VAE vector quantizer. Bitwise-emulates the reference fp32 pipeline:
//   d_k = fl32( fl32(A - 2*M_k) + B_k )
//   A   = sum(x^2)  (float2 leaves + binary tree)   [frozen order]
//   M_k = x . e_k   (sequential ascending-d fp32 FMA chain from 0) [frozen]
//   B_k = sum(e^2)  (sequential ascending chain)    [frozen]
//   argmin, tie -> lowest index.
//
// R9: cp.async register-free staging pipeline over a pre-transposed chunk-
// major codebook (g_Et); one sync per chunk; X/B/chunk0 prefetched under the
// A-phase. atomicMax-complement combine (zero-identity -> no 512KB init);
// all globals self-reset -> tiny prep. Inner math identical to R8.

#define K_CODES   1024
#define D_DIM     64
#define TP        128     // positions per tile
#define TK        128     // codes per chunk
#define NCHUNK    2       // chunks per block (256 codes)
#define NSPLIT    4       // blocks per tile
#define NTILES    512
#define CHF       8192    // floats per transposed chunk (64 d x 128 k)
#define ENC_OFF   4194304
#define LOSS_OFF  4259840
#define NLL_OFF   4259841
#define TOTAL_OUT 4259842

typedef unsigned long long ull;

__device__ double g_loss_acc;            // self-reset by finalizer
__device__ int    g_fin;                 // self-reset by finalizer
__device__ int    g_tcnt[NTILES];        // self-reset by last sibling
__device__ float  g_eB[K_CODES];         // ||e_k||^2, sequential chain (prep)
__device__ float  g_Et[8 * CHF];         // [kc][d][k] transposed codebook (prep)
__device__ ull    g_best[65536];         // ~key per position; 0 = identity

// ---- packed f32x2 helpers (sm_100+); each lane rounds like scalar op ----
__device__ __forceinline__ ull pk2(float a, float b) {
    ull r; asm("mov.b64 %0, {%1, %2};" : "=l"(r) : "f"(a), "f"(b)); return r;
}
__device__ __forceinline__ void upk2(ull v, float& a, float& b) {
    asm("mov.b64 {%0, %1}, %2;" : "=f"(a), "=f"(b) : "l"(v));
}
__device__ __forceinline__ ull ffma2(ull a, ull b, ull c) {
    ull r; asm("fma.rn.f32x2 %0, %1, %2, %3;" : "=l"(r) : "l"(a), "l"(b), "l"(c)); return r;
}
__device__ __forceinline__ ull add2(ull a, ull b) {
    ull r; asm("add.rn.f32x2 %0, %1, %2;" : "=l"(r) : "l"(a), "l"(b)); return r;
}
__device__ __forceinline__ void cp16(unsigned dst, const void* src) {
    asm volatile("cp.async.cg.shared.global [%0], [%1], 16;"
                 :: "r"(dst), "l"(src) : "memory");
}

// Kernel 0: transpose codebook to chunk-major + B_k chains.
__global__ void __launch_bounds__(256) vq_prep(const float* __restrict__ emb) {
    int t = blockIdx.x * blockDim.x + threadIdx.x;   // 256*256 = 65536
    int k = t >> 6, d = t & 63;
    float v = emb[t];                                // coalesced read
    g_Et[(k >> 7) * CHF + d * 128 + (k & 127)] = v;
    if (t < K_CODES) {
        const float* row = emb + (size_t)t * D_DIM;
        float b = 0.0f;
        #pragma unroll
        for (int i = 0; i < 16; i++) {
            float4 w = *(const float4*)(row + i * 4);
            b = __fmaf_rn(w.x, w.x, b);
            b = __fmaf_rn(w.y, w.y, b);
            b = __fmaf_rn(w.z, w.z, b);
            b = __fmaf_rn(w.w, w.w, b);
        }
        g_eB[t] = b;
    }
}

// Main kernel: one block = 128 positions x 256 codes (one K-quarter).
__global__ void __launch_bounds__(256, 2) vq_main(const float* __restrict__ x,
                                                  const float* __restrict__ emb,
                                                  float* __restrict__ out,
                                                  int out_size) {
    extern __shared__ char smem_raw[];
    float* Xs   = (float*)smem_raw;                        // [64][128]    32768 B
    float* Es   = (float*)(smem_raw + 32768);              // [2][64][128] 65536 B
    float* Bs   = (float*)(smem_raw + 32768 + 65536);      // [2][128]      1024 B
    float* As   = (float*)(smem_raw + 99328);              // [128]          512 B
    int*   idx_s = (int*)(smem_raw + 99840);               // [128]          512 B
    // reduction overlays Es buffer 0 (only used after both chunks done):
    float* rV = Es;                                        // [8][128]
    int*   rI = (int*)Es + 1024;                           // [8][128]
    __shared__ int s_flag;

    const unsigned sm_xs = (unsigned)__cvta_generic_to_shared(Xs);
    const unsigned sm_es = (unsigned)__cvta_generic_to_shared(Es);
    const unsigned sm_bs = (unsigned)__cvta_generic_to_shared(Bs);

    const int tid = threadIdx.x;
    const int tx = tid & 31;            // position group (4 positions)
    const int ty = tid >> 5;            // code group (16 codes) — warp-uniform
    const int tile = blockIdx.x >> 2;
    const int ks   = blockIdx.x & 3;    // K-quarter
    const int b  = tile >> 3;
    const int p0 = (tile & 7) * TP;
    const int gbase = b * 1024 + p0;
    const int kq0 = ks * NCHUNK;        // first chunk id for this block

    // ---- prologue: async-copy X tile, E chunk 0, B chunk 0 ----
    {
        const float* xb = x + (size_t)b * 65536 + p0;
        int w = tid >> 5, lane = tid & 31;
        #pragma unroll
        for (int i = 0; i < 8; i++) {
            int d = w + i * 8;
            cp16(sm_xs + d * 512 + lane * 16, xb + d * 1024 + lane * 4);
        }
        const float* esrc = g_Et + kq0 * CHF;
        unsigned boff = (unsigned)((tid >> 5) * 512 + (tid & 31) * 16);
        #pragma unroll
        for (int i = 0; i < 8; i++)
            cp16(sm_es + boff + i * 4096, (const char*)esrc + boff + i * 4096);
        if (tid < 32)
            cp16(sm_bs + tid * 16, g_eB + kq0 * TK + tid * 4);
        asm volatile("cp.async.commit_group;" ::: "memory");
    }

    const ull neg2 = pk2(-2.0f, -2.0f);
    float bv[4];
    int   bi[4];
    #pragma unroll
    for (int i = 0; i < 4; i++) { bv[i] = CUDART_INF_F; bi[i] = 0; }

    // ---- chunk loop: wait -> sync -> (stage next async) -> compute ----
    #pragma unroll 1
    for (int ci = 0; ci < NCHUNK; ci++) {
        asm volatile("cp.async.wait_group 0;" ::: "memory");
        __syncthreads();

        if (ci + 1 < NCHUNK) {   // stage next chunk while computing this one
            const float* esrc = g_Et + (kq0 + ci + 1) * CHF;
            unsigned dbase = sm_es + ((ci + 1) & 1) * 32768;
            unsigned boff = (unsigned)((tid >> 5) * 512 + (tid & 31) * 16);
            #pragma unroll
            for (int i = 0; i < 8; i++)
                cp16(dbase + boff + i * 4096, (const char*)esrc + boff + i * 4096);
            if (tid < 32)
                cp16(sm_bs + 512 + tid * 16, g_eB + (kq0 + 1) * TK + tid * 4);
            asm volatile("cp.async.commit_group;" ::: "memory");
        }

        if (ci == 0) {
            // A_p = sum(x^2): float2 leaves + binary tree (frozen order)
            if (tid < TP) {
                float l[32];
                #pragma unroll
                for (int t = 0; t < 32; t++) {
                    float a = Xs[(2 * t) * TP + tid];
                    float c = Xs[(2 * t + 1) * TP + tid];
                    l[t] = __fmaf_rn(c, c, __fmul_rn(a, a));
                }
                #pragma unroll
                for (int off = 16; off >= 1; off >>= 1)
                    #pragma unroll
                    for (int t = 0; t < 16; t++)
                        if (t < off) l[t] = __fadd_rn(l[t], l[t + off]);
                As[tid] = l[0];
            }
            __syncthreads();
        }

        const int k0 = (kq0 + ci) * TK;
        const float* Eb = Es + (ci & 1) * CHF;
        const float* Bb = Bs + (ci & 1) * TK;

        // compute: acc[4 pos][8 pairs] (16 codes), ascending-d chains
        ull acc[4][8];
        #pragma unroll
        for (int p = 0; p < 4; p++)
            #pragma unroll
            for (int kk = 0; kk < 8; kk++) acc[p][kk] = 0ull;

        #pragma unroll 8
        for (int d = 0; d < D_DIM; d++) {
            const float* Ed = Eb + d * 128 + ty * 16;
            ulonglong2 e01 = *(const ulonglong2*)(Ed + 0);
            ulonglong2 e23 = *(const ulonglong2*)(Ed + 4);
            ulonglong2 e45 = *(const ulonglong2*)(Ed + 8);
            ulonglong2 e67 = *(const ulonglong2*)(Ed + 12);
            float4 xv = *(const float4*)&Xs[d * TP + tx * 4];
            ull ep[8] = { e01.x, e01.y, e23.x, e23.y,
                          e45.x, e45.y, e67.x, e67.y };
            float xs4[4] = { xv.x, xv.y, xv.z, xv.w };
            #pragma unroll
            for (int p = 0; p < 4; p++) {
                ull xp = pk2(xs4[p], xs4[p]);
                #pragma unroll
                for (int kk = 0; kk < 8; kk++)
                    acc[p][kk] = ffma2(xp, ep[kk], acc[p][kk]);
            }
        }

        // fold: d = fl(fl(A - 2M) + B); even code first -> lowest idx on tie
        #pragma unroll
        for (int p = 0; p < 4; p++) {
            float Ap = As[tx * 4 + p];
            ull Apk = pk2(Ap, Ap);
            #pragma unroll
            for (int kk = 0; kk < 8; kk++) {
                ull B2 = ((const ull*)Bb)[ty * 8 + kk];
                ull dpk = add2(ffma2(neg2, acc[p][kk], Apk), B2);
                float d0, d1;
                upk2(dpk, d0, d1);
                int ke = k0 + ty * 16 + 2 * kk;
                if (d0 < bv[p]) { bv[p] = d0; bi[p] = ke; }
                if (d1 < bv[p]) { bv[p] = d1; bi[p] = ke + 1; }
            }
        }
    }

    // ---- cross-ty reduction, then global combine via atomicMax(~key) ----
    __syncthreads();
    #pragma unroll
    for (int p = 0; p < 4; p++) {
        rV[ty * TP + tx * 4 + p] = bv[p];
        rI[ty * TP + tx * 4 + p] = bi[p];
    }
    __syncthreads();
    if (tid < TP) {
        float best = rV[tid];
        int besti  = rI[tid];
        #pragma unroll
        for (int t = 1; t < 8; t++) {
            float v = rV[t * TP + tid];
            int iv  = rI[t * TP + tid];
            if (v < best || (v == best && iv < besti)) { best = v; besti = iv; }
        }
        // d > 0 -> float bits order-isomorphic; min key == max ~key; 0=identity
        ull key = ((ull)__float_as_uint(best) << 32) | (unsigned)besti;
        atomicMax(&g_best[gbase + tid], ~key);
    }

    // ---- last sibling of this tile runs the epilogue ----
    __syncthreads();
    if (tid == 0) {
        __threadfence();
        int old = atomicAdd(&g_tcnt[tile], 1);
        s_flag = (old == NSPLIT - 1);
        if (s_flag) g_tcnt[tile] = 0;          // self-reset for next replay
    }
    __syncthreads();
    if (!s_flag) return;

    // read winners and reset slots to 0 (identity) in one op
    if (tid < TP) {
        ull mk = atomicExch(&g_best[gbase + tid], 0ull);
        int idx = (int)(unsigned)(~mk);
        idx_s[tid] = idx;
        if (out_size >= TOTAL_OUT)
            out[ENC_OFF + gbase + tid] = (float)idx;
    }
    __syncthreads();

    // output (straight-through: x + fl(q - x)) + loss partial
    float lsum = 0.0f;
    #pragma unroll
    for (int j = 0; j < 32; j++) {
        int i  = tid + j * 256;
        int pp = i & 127;
        int d  = i >> 7;
        float q2 = emb[(size_t)idx_s[pp] * 64 + d];
        float xv = Xs[d * TP + pp];
        float df = __fadd_rn(q2, -xv);
        lsum += df * df;
        out[((size_t)b * 64 + d) * 1024 + p0 + pp] = __fadd_rn(xv, df);
    }
    #pragma unroll
    for (int off = 16; off > 0; off >>= 1)
        lsum += __shfl_down_sync(0xffffffffu, lsum, off);
    __shared__ float wsum[8];
    if ((tid & 31) == 0) wsum[tid >> 5] = lsum;
    __syncthreads();
    if (tid == 0) {
        float t = 0.0f;
        #pragma unroll
        for (int w = 0; w < 8; w++) t += wsum[w];
        atomicAdd(&g_loss_acc, (double)t);
        __threadfence();
        int old = atomicAdd(&g_fin, 1);
        if (old == NTILES - 1) {               // final tile writes loss + nll
            if (out_size >= TOTAL_OUT) {
                float m = (float)(g_loss_acc * (1.0 / 4194304.0));
                out[LOSS_OFF] = __fadd_rn(m, __fmul_rn(0.25f, m));
                out[NLL_OFF]  = 1.0f;
            }
            g_loss_acc = 0.0;                  // self-reset for next replay
            g_fin = 0;
        }
    }
}

extern "C" void kernel_launch(void* const* d_in, const int* in_sizes, int n_in,
                              void* d_out, int out_size) {
    const float* x   = (const float*)d_in[0];
    const float* emb = (const float*)d_in[1];
    if (n_in >= 2 && in_sizes[0] == K_CODES * D_DIM) {
        const float* t = x; x = emb; emb = t;
    }
    float* out = (float*)d_out;

    const int smem_bytes = 32768 + 65536 + 1024 + 512 + 512;   // 100352
    cudaFuncSetAttribute(vq_main, cudaFuncAttributeMaxDynamicSharedMemorySize,
                         smem_bytes);

    vq_prep<<<256, 256>>>(emb);
    vq_main<<<2048, 256, smem_bytes>>>(x, emb, out, out_size);
}